// round 9
// baseline (speedup 1.0000x reference)
#include <cuda_runtime.h>
#include <cuda_bf16.h>
#include <cfloat>
#include <cstdint>

// Problem constants (fixed by setup_inputs)
#define BATCH 32
#define CH    512
#define TLEN  128
#define NROI  128
#define OBINS 64
#define BINSZ 8                              // CH / OBINS
#define NROIS_TOTAL (BATCH * NROI)           // 4096
#define POOLED_ELEMS (NROIS_TOTAL * OBINS)   // 262144

#define SPLIT_O 16                           // o-groups per batch
#define OB (OBINS / SPLIT_O)                 // 4 bins per block (1 per warp)
#define NTHREADS 128                         // 4 warps
#define LVPITCH 132                          // floats between levels (528 B)
#define STPITCH 5                            // staging pitch (coprime 32)

__device__ __forceinline__ float4 f4max(float4 a, float4 b) {
    float4 r;
    r.x = fmaxf(a.x, b.x); r.y = fmaxf(a.y, b.y);
    r.z = fmaxf(a.z, b.z); r.w = fmaxf(a.w, b.w);
    return r;
}

// Fused, warp-autonomous. Grid = 32x16 = 512 blocks (~3.5/SM), 128 threads.
// Warp w owns bin og*4+w. Lane = t-quad. Per warp: prefetch 4 ROI spans,
// 8 coalesced LDG.128 (the bin's 8 channels), fold to L0 in regs, build
// sparse range-max levels L1..L4 via shuffles, store to smem, answer each
// ROI with 2 lookups + 1 fmax. One __syncthreads for the output transpose.
__global__ void __launch_bounds__(NTHREADS, 8)
roipool_fused(const float* __restrict__ feat,
              const int* __restrict__ tois,
              float* __restrict__ out) {
    const int tid = threadIdx.x;
    const int w   = tid >> 5;                // warp = bin within group (0..3)
    const int l   = tid & 31;                // lane = t-quad
    const int b   = blockIdx.x >> 4;         // batch
    const int og  = blockIdx.x & 15;         // bin-group

    __shared__ alignas(16) float lv[OB][5 * LVPITCH];  // levels, ~10.5 KB
    __shared__ float st[NROI * STPITCH];               // staging [rl][o], 2.5 KB

    // ---- prefetch this lane's 4 ROI spans first (tiny, L2-resident) ----
    const int2* tp = (const int2*)(tois) + b * NROI;
    int2 se0 = __ldg(&tp[l]);
    int2 se1 = __ldg(&tp[l + 32]);
    int2 se2 = __ldg(&tp[l + 64]);
    int2 se3 = __ldg(&tp[l + 96]);

    // ---- Phase 1: 8 coalesced LDG.128 of this bin's channels, fold ----
    const float4* p = (const float4*)(feat
        + ((size_t)b * CH + (size_t)(og * OB + w) * BINSZ) * TLEN) + l;
    float4 v0 = p[0 * 32], v1 = p[1 * 32], v2 = p[2 * 32], v3 = p[3 * 32];
    float4 v4 = p[4 * 32], v5 = p[5 * 32], v6 = p[6 * 32], v7 = p[7 * 32];
    float4 a = f4max(f4max(f4max(v0, v1), f4max(v2, v3)),
                     f4max(f4max(v4, v5), f4max(v6, v7)));   // L0[4l..4l+3]

    // ---- sparse-max levels in registers via shuffles ----
    const unsigned FULL = 0xffffffffu;
    float nx = __shfl_down_sync(FULL, a.x, 1);
    float4 bq = make_float4(fmaxf(a.x, a.y), fmaxf(a.y, a.z),
                            fmaxf(a.z, a.w), fmaxf(a.w, nx));
    float nb0 = __shfl_down_sync(FULL, bq.x, 1);
    float nb1 = __shfl_down_sync(FULL, bq.y, 1);
    float4 cq = make_float4(fmaxf(bq.x, bq.z), fmaxf(bq.y, bq.w),
                            fmaxf(bq.z, nb0), fmaxf(bq.w, nb1));
    float4 nc;
    nc.x = __shfl_down_sync(FULL, cq.x, 1); nc.y = __shfl_down_sync(FULL, cq.y, 1);
    nc.z = __shfl_down_sync(FULL, cq.z, 1); nc.w = __shfl_down_sync(FULL, cq.w, 1);
    float4 dq = f4max(cq, nc);
    float4 nd;
    nd.x = __shfl_down_sync(FULL, dq.x, 2); nd.y = __shfl_down_sync(FULL, dq.y, 2);
    nd.z = __shfl_down_sync(FULL, dq.z, 2); nd.w = __shfl_down_sync(FULL, dq.w, 2);
    float4 eq = f4max(dq, nd);
    // (Clamped-shuffle garbage only at t > 128-2^k; such entries are never
    //  queried since a level-k lookup has t <= 128 - 2^k.)

    // ---- store levels (STS.128, lane-consecutive, conflict-free) ----
    *(float4*)&lv[w][0 * LVPITCH + 4 * l] = a;
    *(float4*)&lv[w][1 * LVPITCH + 4 * l] = bq;
    *(float4*)&lv[w][2 * LVPITCH + 4 * l] = cq;
    *(float4*)&lv[w][3 * LVPITCH + 4 * l] = dq;
    *(float4*)&lv[w][4 * LVPITCH + 4 * l] = eq;
    __syncwarp();

    // ---- Phase 2: 128 ROIs for this bin, 4 per lane, 2 lookups each ----
#pragma unroll
    for (int i = 0; i < 4; i++) {
        const int2 se = (i == 0) ? se0 : (i == 1) ? se1 : (i == 2) ? se2 : se3;
        const int rl = l + 32 * i;
        const int len = se.y - se.x;         // 1..16
        const int k = 31 - __clz(len);       // floor(log2 len), 0..4
        const float* Lk = &lv[w][k * LVPITCH];
        float m = fmaxf(Lk[se.x], Lk[se.y - (1 << k)]);
        st[rl * STPITCH + w] = m;            // pitch 5 coprime 32 -> no conflicts
    }
    __syncthreads();

    // ---- writeout: thread = ROI, one float4 (this block's 4 bins) ----
    {
        const int r = tid;                   // 0..127
        float4 v = make_float4(st[r * STPITCH + 0], st[r * STPITCH + 1],
                               st[r * STPITCH + 2], st[r * STPITCH + 3]);
        *(float4*)&out[(size_t)(b * NROI + r) * OBINS + og * OB] = v;
    }

    // ---- offsets tail (float-encoded in the unified f32 output buffer) ----
    if (blockIdx.x == 0 && tid < BATCH) {
        out[POOLED_ELEMS + tid] = (float)((tid + 1) * NROI);
    }
}

extern "C" void kernel_launch(void* const* d_in, const int* in_sizes, int n_in,
                              void* d_out, int out_size) {
    const float* feat = (const float*)d_in[0];   // [32, 512, 128] f32
    const int*   tois = (const int*)d_in[1];     // [32, 128, 2] i32
    float* out = (float*)d_out;

    roipool_fused<<<BATCH * SPLIT_O, NTHREADS>>>(feat, tois, out);
}